// round 2
// baseline (speedup 1.0000x reference)
#include <cuda_runtime.h>
#include <math.h>

#define NB   2048
#define NSEQ 49
#define ND   384
#define NH   12
#define NHD  32
#define NROWS (NB*NSEQ)   // 100352

// Scratch (device globals — no allocation allowed)
__device__ float g_q[(size_t)NB*NH*NSEQ*NHD];    // [B,H,S,hd]
__device__ float g_k[(size_t)NB*NH*NSEQ*NHD];
__device__ float g_v[(size_t)NB*NH*NSEQ*NHD];
__device__ float g_att[(size_t)NROWS*ND];        // [B,S,D]

// ---------------------------------------------------------------------------
// Tiled SGEMM core: C[128x128] tile of  A[M,K] @ W[N,K]^T   (K = 384)
// 256 threads, 8x8 microtile, BK=16, double-buffered smem.
// ---------------------------------------------------------------------------

#define GEMM_PROLOG(APTR)                                                     \
    __shared__ __align__(16) float As[2][16][132];                            \
    __shared__ __align__(16) float Bs[2][16][132];                            \
    const int K = 384;                                                        \
    const int NK = K / 16;                                                    \
    int bm = blockIdx.y * 128;                                                \
    int bn = blockIdx.x * 128;                                                \
    int tid = threadIdx.x;                                                    \
    int tn = tid & 15, tm = tid >> 4;                                         \
    int la0 = tid, la1 = tid + 256;                                           \
    int lm0 = la0 >> 2, lq0 = la0 & 3;                                        \
    int lm1 = la1 >> 2, lq1 = la1 & 3;                                        \
    const float* Aptr0 = (APTR) + (size_t)(bm + lm0) * K + lq0 * 4;           \
    const float* Aptr1 = (APTR) + (size_t)(bm + lm1) * K + lq1 * 4;           \
    const float* Wptr0 = W + (size_t)(bn + lm0) * K + lq0 * 4;                \
    const float* Wptr1 = W + (size_t)(bn + lm1) * K + lq1 * 4;                \
    float4 ra0 = *(const float4*)Aptr0;                                       \
    float4 ra1 = *(const float4*)Aptr1;                                       \
    float4 rb0 = *(const float4*)Wptr0;                                       \
    float4 rb1 = *(const float4*)Wptr1;                                       \
    float acc[8][8];                                                          \
    _Pragma("unroll")                                                         \
    for (int i = 0; i < 8; i++)                                               \
        _Pragma("unroll")                                                     \
        for (int j = 0; j < 8; j++) acc[i][j] = 0.f;

#define STS_TILE(BUF)                                                         \
    As[BUF][lq0*4+0][lm0] = ra0.x; As[BUF][lq0*4+1][lm0] = ra0.y;             \
    As[BUF][lq0*4+2][lm0] = ra0.z; As[BUF][lq0*4+3][lm0] = ra0.w;             \
    As[BUF][lq1*4+0][lm1] = ra1.x; As[BUF][lq1*4+1][lm1] = ra1.y;             \
    As[BUF][lq1*4+2][lm1] = ra1.z; As[BUF][lq1*4+3][lm1] = ra1.w;             \
    Bs[BUF][lq0*4+0][lm0] = rb0.x; Bs[BUF][lq0*4+1][lm0] = rb0.y;             \
    Bs[BUF][lq0*4+2][lm0] = rb0.z; Bs[BUF][lq0*4+3][lm0] = rb0.w;             \
    Bs[BUF][lq1*4+0][lm1] = rb1.x; Bs[BUF][lq1*4+1][lm1] = rb1.y;             \
    Bs[BUF][lq1*4+2][lm1] = rb1.z; Bs[BUF][lq1*4+3][lm1] = rb1.w;

#define GEMM_MAINLOOP                                                         \
    { STS_TILE(0); }                                                          \
    __syncthreads();                                                          \
    for (int kt = 0; kt < NK; kt++) {                                         \
        int buf = kt & 1;                                                     \
        if (kt + 1 < NK) {                                                    \
            int ko = (kt + 1) * 16;                                           \
            ra0 = *(const float4*)(Aptr0 + ko);                               \
            ra1 = *(const float4*)(Aptr1 + ko);                               \
            rb0 = *(const float4*)(Wptr0 + ko);                               \
            rb1 = *(const float4*)(Wptr1 + ko);                               \
        }                                                                     \
        _Pragma("unroll")                                                     \
        for (int kk = 0; kk < 16; kk++) {                                     \
            float4 a0 = *(const float4*)&As[buf][kk][tm * 4];                 \
            float4 a1 = *(const float4*)&As[buf][kk][64 + tm * 4];            \
            float4 b0 = *(const float4*)&Bs[buf][kk][tn * 4];                 \
            float4 b1 = *(const float4*)&Bs[buf][kk][64 + tn * 4];            \
            float fa[8] = {a0.x,a0.y,a0.z,a0.w,a1.x,a1.y,a1.z,a1.w};          \
            float fb[8] = {b0.x,b0.y,b0.z,b0.w,b1.x,b1.y,b1.z,b1.w};          \
            _Pragma("unroll")                                                 \
            for (int i = 0; i < 8; i++)                                       \
                _Pragma("unroll")                                             \
                for (int j = 0; j < 8; j++)                                   \
                    acc[i][j] += fa[i] * fb[j];                               \
        }                                                                     \
        if (kt + 1 < NK) {                                                    \
            int nbuf = buf ^ 1;                                               \
            STS_TILE(nbuf);                                                   \
            __syncthreads();                                                  \
        }                                                                     \
    }

// ---------------------------------------------------------------------------
// Kernel 1: QKV projection. C = hidden @ w_qkv^T + b_qkv, scattered into
// per-head q/k/v scratch with layout [B,H,S,hd]. Q is pre-scaled by
// 1/sqrt(hd) so the attention kernel skips the per-score multiply.
// ---------------------------------------------------------------------------
__global__ void __launch_bounds__(256)
gemm_qkv_kernel(const float* __restrict__ A,     // [NROWS, 384]
                const float* __restrict__ W,     // [1152, 384]
                const float* __restrict__ bias)  // [1152]
{
    GEMM_PROLOG(A)
    GEMM_MAINLOOP

    int brow[8], srow[8];
#pragma unroll
    for (int i = 0; i < 8; i++) {
        int m = bm + tm * 4 + (i & 3) + ((i >= 4) ? 64 : 0);
        brow[i] = m / 49;
        srow[i] = m - brow[i] * 49;
    }
#pragma unroll
    for (int g = 0; g < 2; g++) {
        int n0 = bn + g * 64 + tn * 4;
        int part = n0 / 384;
        int rem = n0 - part * 384;
        int h = rem >> 5, d = rem & 31;
        float* base = (part == 0) ? g_q : (part == 1) ? g_k : g_v;
        float sc = (part == 0) ? 0.17677669529663687f : 1.0f;  // 1/sqrt(32)
        float4 bb = *(const float4*)&bias[n0];
#pragma unroll
        for (int i = 0; i < 8; i++) {
            size_t idx = ((size_t)((brow[i] * 12 + h) * 49 + srow[i]) << 5) + d;
            float4 v;
            v.x = (acc[i][g * 4 + 0] + bb.x) * sc;
            v.y = (acc[i][g * 4 + 1] + bb.y) * sc;
            v.z = (acc[i][g * 4 + 2] + bb.z) * sc;
            v.w = (acc[i][g * 4 + 3] + bb.w) * sc;
            *(float4*)&base[idx] = v;
        }
    }
}

// ---------------------------------------------------------------------------
// Kernel 2: per-(window, head) attention.
//   scores = Qs@K^T + rel_bias(gathered) + mask ; softmax ; @V
// One CTA per (b,h); everything in smem. Q comes in pre-scaled.
// ---------------------------------------------------------------------------
__global__ void __launch_bounds__(128)
attn_kernel(const float* __restrict__ mask,    // [B,49,49]
            const float* __restrict__ table)   // [169,12]
{
    int bh = blockIdx.x;
    int b = bh / 12, h = bh - b * 12;
    __shared__ __align__(16) float qs[49 * 32];
    __shared__ __align__(16) float ks[49 * 32];
    __shared__ __align__(16) float vs[49 * 32];
    __shared__ float sc[49][52];
    int tid = threadIdx.x;

    const float* qg = g_q + (size_t)bh * 49 * 32;
    const float* kg = g_k + (size_t)bh * 49 * 32;
    const float* vg = g_v + (size_t)bh * 49 * 32;
    for (int i = tid; i < 49 * 32; i += 128) {
        qs[i] = qg[i];
        ks[i] = kg[i];
        vs[i] = vg[i];
    }
    __syncthreads();

    const float* mrow = mask + (size_t)b * 49 * 49;

    for (int e = tid; e < 49 * 49; e += 128) {
        int i = e / 49, j = e - i * 49;
        const float4* qp = (const float4*)(qs + i * 32);
        const float4* kp = (const float4*)(ks + j * 32);
        float a = 0.f;
#pragma unroll
        for (int t = 0; t < 8; t++) {
            float4 x = qp[t], y = kp[t];
            a += x.x * y.x + x.y * y.y + x.z * y.z + x.w * y.w;
        }
        int yi = i / 7, xi = i - yi * 7;
        int yj = j / 7, xj = j - yj * 7;
        int ridx = (yi - yj + 6) * 13 + (xi - xj + 6);
        sc[i][j] = a + table[ridx * 12 + h] + mrow[e];
    }
    __syncthreads();

    if (tid < 49) {
        float mx = -INFINITY;
#pragma unroll 7
        for (int j = 0; j < 49; j++) mx = fmaxf(mx, sc[tid][j]);
        float sum = 0.f;
#pragma unroll 7
        for (int j = 0; j < 49; j++) {
            float ev = __expf(sc[tid][j] - mx);
            sc[tid][j] = ev;
            sum += ev;
        }
        float inv = 1.f / sum;
#pragma unroll 7
        for (int j = 0; j < 49; j++) sc[tid][j] *= inv;
    }
    __syncthreads();

    float* attp = g_att + (size_t)b * 49 * 384 + h * 32;
    for (int e = tid; e < 49 * 32; e += 128) {
        int i = e >> 5, d = e & 31;
        float a = 0.f;
#pragma unroll 7
        for (int j = 0; j < 49; j++) a += sc[i][j] * vs[j * 32 + d];
        attp[(size_t)i * 384 + d] = a;
    }
}

// ---------------------------------------------------------------------------
// Kernel 3: output projection. out = g_att @ w_out^T + b_out
// ---------------------------------------------------------------------------
__global__ void __launch_bounds__(256)
gemm_out_kernel(const float* __restrict__ W,     // [384, 384]
                const float* __restrict__ bias,  // [384]
                float* __restrict__ C)           // [NROWS, 384]
{
    const float* A = g_att;
    GEMM_PROLOG(A)
    GEMM_MAINLOOP

    int mg[8];
#pragma unroll
    for (int i = 0; i < 8; i++)
        mg[i] = bm + tm * 4 + (i & 3) + ((i >= 4) ? 64 : 0);
#pragma unroll
    for (int g = 0; g < 2; g++) {
        int n0 = bn + g * 64 + tn * 4;
        float4 bb = *(const float4*)&bias[n0];
#pragma unroll
        for (int i = 0; i < 8; i++) {
            float4 v;
            v.x = acc[i][g * 4 + 0] + bb.x;
            v.y = acc[i][g * 4 + 1] + bb.y;
            v.z = acc[i][g * 4 + 2] + bb.z;
            v.w = acc[i][g * 4 + 3] + bb.w;
            *(float4*)&C[(size_t)mg[i] * 384 + n0] = v;
        }
    }
}

// ---------------------------------------------------------------------------
extern "C" void kernel_launch(void* const* d_in, const int* in_sizes, int n_in,
                              void* d_out, int out_size)
{
    const float* hidden = (const float*)d_in[0];
    const float* mask   = (const float*)d_in[1];
    const float* w_qkv  = (const float*)d_in[2];
    const float* b_qkv  = (const float*)d_in[3];
    const float* w_out  = (const float*)d_in[4];
    const float* b_out  = (const float*)d_in[5];
    const float* table  = (const float*)d_in[6];
    float* out = (float*)d_out;

    gemm_qkv_kernel<<<dim3(1152 / 128, NROWS / 128), 256>>>(hidden, w_qkv, b_qkv);
    attn_kernel<<<NB * NH, 128>>>(mask, table);
    gemm_out_kernel<<<dim3(384 / 128, NROWS / 128), 256>>>(w_out, b_out, out);
}

// round 4
// speedup vs baseline: 1.3111x; 1.3111x over previous
#include <cuda_runtime.h>
#include <cuda_bf16.h>
#include <math.h>
#include <stdint.h>

#define NB   2048
#define NSEQ 49
#define ND   384
#define NH   12
#define NHD  32
#define NROWS (NB*NSEQ)   // 100352

// Scratch (device globals — no allocation allowed)
__device__ float g_q[(size_t)NB*NH*NSEQ*NHD];    // [B,H,S,hd]
__device__ float g_k[(size_t)NB*NH*NSEQ*NHD];
__device__ float g_v[(size_t)NB*NH*NSEQ*NHD];
__device__ float g_att[(size_t)NROWS*ND];        // [B,S,D]

// ===========================================================================
// helpers
// ===========================================================================
__device__ __forceinline__ uint32_t smem_u32(const void* p) {
    uint32_t a;
    asm("{ .reg .u64 t; cvta.to.shared.u64 t, %1; cvt.u32.u64 %0, t; }"
        : "=r"(a) : "l"(p));
    return a;
}
__device__ __forceinline__ void ldsm4(uint32_t* r, uint32_t addr) {
    asm volatile("ldmatrix.sync.aligned.m8n8.x4.shared.b16 {%0,%1,%2,%3}, [%4];"
        : "=r"(r[0]), "=r"(r[1]), "=r"(r[2]), "=r"(r[3]) : "r"(addr));
}
__device__ __forceinline__ void mma16816(float* c, const uint32_t* a, const uint32_t* b) {
    asm volatile("mma.sync.aligned.m16n8k16.row.col.f32.bf16.bf16.f32 "
        "{%0,%1,%2,%3}, {%4,%5,%6,%7}, {%8,%9}, {%0,%1,%2,%3};"
        : "+f"(c[0]), "+f"(c[1]), "+f"(c[2]), "+f"(c[3])
        : "r"(a[0]), "r"(a[1]), "r"(a[2]), "r"(a[3]), "r"(b[0]), "r"(b[1]));
}
#define STS128(a, r0, r1, r2, r3) \
    asm volatile("st.shared.v4.b32 [%0], {%1, %2, %3, %4};" \
                 :: "r"(a), "r"(r0), "r"(r1), "r"(r2), "r"(r3) : "memory")

// split fp32 -> bf16 hi/lo, 8 values -> two uint4 (packed bf16x2)
__device__ __forceinline__ void cvt8_hilo(float4 x0, float4 x1, uint4& hi, uint4& lo) {
    float f[8] = {x0.x, x0.y, x0.z, x0.w, x1.x, x1.y, x1.z, x1.w};
    uint32_t h[8], l[8];
#pragma unroll
    for (int i = 0; i < 8; i++) {
        __nv_bfloat16 hb = __float2bfloat16(f[i]);
        __nv_bfloat16 lb = __float2bfloat16(f[i] - __bfloat162float(hb));
        h[i] = (uint32_t)__bfloat16_as_ushort(hb);
        l[i] = (uint32_t)__bfloat16_as_ushort(lb);
    }
    hi = make_uint4(h[0] | (h[1] << 16), h[2] | (h[3] << 16),
                    h[4] | (h[5] << 16), h[6] | (h[7] << 16));
    lo = make_uint4(l[0] | (l[1] << 16), l[2] | (l[3] << 16),
                    l[4] | (l[5] << 16), l[6] | (l[7] << 16));
}

// ===========================================================================
// HMMA GEMM mainloop: acc[128x128] tile of A[M,384] @ W[N,384]^T, bf16 hi/lo
// 3-product split for ~fp32 accuracy. 256 threads = 8 warps (warp wm=wid>>2
// in {0,1} owns 64 rows; wn=wid&3 owns 32 cols). BK=32, 12 k-steps,
// double-buffered smem.
// smem layout (per buffer, row stride 40 bf16 = 80B):
//   Ah @ 0, Al @ 10240, Bh @ 20480, Bl @ 30720 ; buffer stride 40960.
// ===========================================================================
#define OFF_AL 10240u
#define OFF_BH 20480u
#define OFF_BL 30720u
#define BUFSTRIDE 40960u

__device__ __forceinline__ void gemm_mainloop(
    const float* __restrict__ Abase, const float* __restrict__ Wbase,
    int bm, int bn, int tid, float acc[4][4][4])
{
    extern __shared__ char smem[];
    uint32_t sb = smem_u32(smem);
    int wid = tid >> 5, l = tid & 31;
    int wm = wid >> 2, wn = wid & 3;

    const float* arow = Abase + (size_t)(bm + (tid >> 1)) * 384 + (tid & 1) * 16;
    const float* wrow = Wbase + (size_t)(bn + (tid >> 1)) * 384 + (tid & 1) * 16;
    uint32_t sts_off = (uint32_t)((tid >> 1) * 80 + (tid & 1) * 32);

#pragma unroll
    for (int mi = 0; mi < 4; mi++)
#pragma unroll
        for (int nj = 0; nj < 4; nj++)
#pragma unroll
            for (int r = 0; r < 4; r++) acc[mi][nj][r] = 0.f;

    // fragment addresses (byte offsets within a tile)
    uint32_t a_fo[4], b_fo[2];
#pragma unroll
    for (int mi = 0; mi < 4; mi++) {
        int row = wm * 64 + mi * 16 + (l & 15);
        int col = (l >> 4) << 3;
        a_fo[mi] = (uint32_t)(row * 80 + col * 2);
    }
#pragma unroll
    for (int p = 0; p < 2; p++) {
        int row = wn * 32 + p * 16 + (l & 7) + ((l >> 4) << 3);
        int col = ((l >> 3) & 1) << 3;
        b_fo[p] = (uint32_t)(row * 80 + col * 2);
    }

    float4 pa[4], pb[4];
#pragma unroll
    for (int g = 0; g < 4; g++) {
        pa[g] = *(const float4*)(arow + g * 4);
        pb[g] = *(const float4*)(wrow + g * 4);
    }
    // fill buffer 0
    {
        uint32_t base = sb;
#pragma unroll
        for (int h2 = 0; h2 < 2; h2++) {
            uint4 hi, lo;
            cvt8_hilo(pa[h2 * 2], pa[h2 * 2 + 1], hi, lo);
            STS128(base + sts_off + h2 * 16, hi.x, hi.y, hi.z, hi.w);
            STS128(base + OFF_AL + sts_off + h2 * 16, lo.x, lo.y, lo.z, lo.w);
            cvt8_hilo(pb[h2 * 2], pb[h2 * 2 + 1], hi, lo);
            STS128(base + OFF_BH + sts_off + h2 * 16, hi.x, hi.y, hi.z, hi.w);
            STS128(base + OFF_BL + sts_off + h2 * 16, lo.x, lo.y, lo.z, lo.w);
        }
    }
    __syncthreads();

    for (int kt = 0; kt < 12; kt++) {
        if (kt + 1 < 12) {
            int ko = (kt + 1) * 32;
#pragma unroll
            for (int g = 0; g < 4; g++) {
                pa[g] = *(const float4*)(arow + ko + g * 4);
                pb[g] = *(const float4*)(wrow + ko + g * 4);
            }
        }
        uint32_t cbase = sb + (kt & 1) * BUFSTRIDE;
#pragma unroll
        for (int kk = 0; kk < 2; kk++) {
            uint32_t kof = kk * 16;  // bf16 cols -> *2 bytes
            uint32_t ah[4][4], al_[4][4], bh[2][4], bl_[2][4];
#pragma unroll
            for (int mi = 0; mi < 4; mi++) {
                ldsm4(ah[mi], cbase + a_fo[mi] + kof * 2);
                ldsm4(al_[mi], cbase + OFF_AL + a_fo[mi] + kof * 2);
            }
#pragma unroll
            for (int p = 0; p < 2; p++) {
                ldsm4(bh[p], cbase + OFF_BH + b_fo[p] + kof * 2);
                ldsm4(bl_[p], cbase + OFF_BL + b_fo[p] + kof * 2);
            }
#pragma unroll
            for (int mi = 0; mi < 4; mi++)
#pragma unroll
                for (int nj = 0; nj < 4; nj++)
                    mma16816(acc[mi][nj], ah[mi], &bh[nj >> 1][(nj & 1) * 2]);
#pragma unroll
            for (int mi = 0; mi < 4; mi++)
#pragma unroll
                for (int nj = 0; nj < 4; nj++)
                    mma16816(acc[mi][nj], ah[mi], &bl_[nj >> 1][(nj & 1) * 2]);
#pragma unroll
            for (int mi = 0; mi < 4; mi++)
#pragma unroll
                for (int nj = 0; nj < 4; nj++)
                    mma16816(acc[mi][nj], al_[mi], &bh[nj >> 1][(nj & 1) * 2]);
        }
        if (kt + 1 < 12) {
            uint32_t nbase = sb + ((kt + 1) & 1) * BUFSTRIDE;
#pragma unroll
            for (int h2 = 0; h2 < 2; h2++) {
                uint4 hi, lo;
                cvt8_hilo(pa[h2 * 2], pa[h2 * 2 + 1], hi, lo);
                STS128(nbase + sts_off + h2 * 16, hi.x, hi.y, hi.z, hi.w);
                STS128(nbase + OFF_AL + sts_off + h2 * 16, lo.x, lo.y, lo.z, lo.w);
                cvt8_hilo(pb[h2 * 2], pb[h2 * 2 + 1], hi, lo);
                STS128(nbase + OFF_BH + sts_off + h2 * 16, hi.x, hi.y, hi.z, hi.w);
                STS128(nbase + OFF_BL + sts_off + h2 * 16, lo.x, lo.y, lo.z, lo.w);
            }
        }
        __syncthreads();
    }
}

// ---------------------------------------------------------------------------
// Kernel 1: QKV projection -> scatter to g_q/g_k/g_v [B,H,S,hd], q pre-scaled.
// ---------------------------------------------------------------------------
__global__ void __launch_bounds__(256)
mma_qkv_kernel(const float* __restrict__ A,     // [NROWS,384]
               const float* __restrict__ W,     // [1152,384]
               const float* __restrict__ bias)  // [1152]
{
    int tid = threadIdx.x;
    int bm = blockIdx.y * 128, bn = blockIdx.x * 128;
    float acc[4][4][4];
    gemm_mainloop(A, W, bm, bn, tid, acc);

    int wid = tid >> 5, l = tid & 31;
    int wm = wid >> 2, wn = wid & 3;
    int part = bn / 384;
    int h = ((bn % 384) + wn * 32) >> 5;
    const float scl = (part == 0) ? 0.17677669529663687f : 1.0f;
    float* base = (part == 0) ? g_q : (part == 1) ? g_k : g_v;

#pragma unroll
    for (int mi = 0; mi < 4; mi++) {
#pragma unroll
        for (int nj = 0; nj < 4; nj++) {
            int n = bn + wn * 32 + nj * 8 + (l & 3) * 2;
            int d = nj * 8 + (l & 3) * 2;
            float b0 = bias[n], b1 = bias[n + 1];
#pragma unroll
            for (int rh = 0; rh < 2; rh++) {
                int row = bm + wm * 64 + mi * 16 + (l >> 2) + rh * 8;
                int b = row / 49, s = row - b * 49;
                size_t o = (((size_t)(b * 12 + h) * 49 + s) << 5) + d;
                float2 v;
                v.x = (acc[mi][nj][rh * 2 + 0] + b0) * scl;
                v.y = (acc[mi][nj][rh * 2 + 1] + b1) * scl;
                *(float2*)&base[o] = v;
            }
        }
    }
}

// ---------------------------------------------------------------------------
// Kernel 3: output projection. out = g_att @ w_out^T + b_out.
// ---------------------------------------------------------------------------
__global__ void __launch_bounds__(256)
mma_out_kernel(const float* __restrict__ W,     // [384,384]
               const float* __restrict__ bias,  // [384]
               float* __restrict__ C)           // [NROWS,384]
{
    int tid = threadIdx.x;
    int bm = blockIdx.y * 128, bn = blockIdx.x * 128;
    float acc[4][4][4];
    gemm_mainloop(g_att, W, bm, bn, tid, acc);

    int wid = tid >> 5, l = tid & 31;
    int wm = wid >> 2, wn = wid & 3;
#pragma unroll
    for (int mi = 0; mi < 4; mi++) {
#pragma unroll
        for (int nj = 0; nj < 4; nj++) {
            int n = bn + wn * 32 + nj * 8 + (l & 3) * 2;
            float b0 = bias[n], b1 = bias[n + 1];
#pragma unroll
            for (int rh = 0; rh < 2; rh++) {
                int row = bm + wm * 64 + mi * 16 + (l >> 2) + rh * 8;
                float2 v;
                v.x = acc[mi][nj][rh * 2 + 0] + b0;
                v.y = acc[mi][nj][rh * 2 + 1] + b1;
                *(float2*)&C[(size_t)row * 384 + n] = v;
            }
        }
    }
}

// ---------------------------------------------------------------------------
// Kernel 2: per-(window, head) attention.
// scores elementwise; softmax warp-per-row (shfl reductions); PV float4.
// ---------------------------------------------------------------------------
__global__ void __launch_bounds__(128)
attn_kernel(const float* __restrict__ mask,    // [B,49,49]
            const float* __restrict__ table)   // [169,12]
{
    int bh = blockIdx.x;
    int b = bh / 12, h = bh - b * 12;
    __shared__ __align__(16) float qs[49 * 32];
    __shared__ __align__(16) float ks[49 * 32];
    __shared__ __align__(16) float vs[49 * 32];
    __shared__ float sc[49][52];
    int tid = threadIdx.x;
    int wid = tid >> 5, lid = tid & 31;

    const float4* qg = (const float4*)(g_q + (size_t)bh * 49 * 32);
    const float4* kg = (const float4*)(g_k + (size_t)bh * 49 * 32);
    const float4* vg = (const float4*)(g_v + (size_t)bh * 49 * 32);
    for (int i = tid; i < 392; i += 128) {
        ((float4*)qs)[i] = qg[i];
        ((float4*)ks)[i] = kg[i];
        ((float4*)vs)[i] = vg[i];
    }
    __syncthreads();

    const float* mrow = mask + (size_t)b * 49 * 49;
    for (int e = tid; e < 49 * 49; e += 128) {
        int i = e / 49, j = e - i * 49;
        const float4* qp = (const float4*)(qs + i * 32);
        const float4* kp = (const float4*)(ks + j * 32);
        float a = 0.f;
#pragma unroll
        for (int t = 0; t < 8; t++) {
            float4 x = qp[t], y = kp[t];
            a += x.x * y.x + x.y * y.y + x.z * y.z + x.w * y.w;
        }
        int yi = i / 7, xi = i - yi * 7;
        int yj = j / 7, xj = j - yj * 7;
        int ridx = (yi - yj + 6) * 13 + (xi - xj + 6);
        sc[i][j] = a + table[ridx * 12 + h] + mrow[e];
    }
    __syncthreads();

    // softmax: one warp per row, rows wid, wid+4, ...
    for (int i = wid; i < 49; i += 4) {
        float v0 = sc[i][lid];
        float v1 = (lid < 17) ? sc[i][lid + 32] : -INFINITY;
        float mx = fmaxf(v0, v1);
#pragma unroll
        for (int off = 16; off; off >>= 1)
            mx = fmaxf(mx, __shfl_xor_sync(0xFFFFFFFFu, mx, off));
        float e0 = __expf(v0 - mx);
        float e1 = (lid < 17) ? __expf(v1 - mx) : 0.f;
        float s = e0 + e1;
#pragma unroll
        for (int off = 16; off; off >>= 1)
            s += __shfl_xor_sync(0xFFFFFFFFu, s, off);
        float inv = 1.f / s;
        sc[i][lid] = e0 * inv;
        if (lid < 17) sc[i][lid + 32] = e1 * inv;
    }
    __syncthreads();

    // PV: each thread owns (i, d4) float4 outputs
    float* attp = g_att + (size_t)b * 49 * 384 + h * 32;
    for (int e = tid; e < 392; e += 128) {
        int i = e >> 3, d4 = e & 7;
        float4 a = make_float4(0.f, 0.f, 0.f, 0.f);
#pragma unroll 7
        for (int j = 0; j < 49; j++) {
            float s = sc[i][j];
            float4 v = *(const float4*)&vs[j * 32 + d4 * 4];
            a.x += s * v.x; a.y += s * v.y; a.z += s * v.z; a.w += s * v.w;
        }
        *(float4*)&attp[(size_t)i * 384 + d4 * 4] = a;
    }
}

// ---------------------------------------------------------------------------
extern "C" void kernel_launch(void* const* d_in, const int* in_sizes, int n_in,
                              void* d_out, int out_size)
{
    const float* hidden = (const float*)d_in[0];
    const float* mask   = (const float*)d_in[1];
    const float* w_qkv  = (const float*)d_in[2];
    const float* b_qkv  = (const float*)d_in[3];
    const float* w_out  = (const float*)d_in[4];
    const float* b_out  = (const float*)d_in[5];
    const float* table  = (const float*)d_in[6];
    float* out = (float*)d_out;

    const int SMEM_BYTES = 81920;  // 2 buffers x 4 tiles x 10240
    cudaFuncSetAttribute(mma_qkv_kernel, cudaFuncAttributeMaxDynamicSharedMemorySize, SMEM_BYTES);
    cudaFuncSetAttribute(mma_out_kernel, cudaFuncAttributeMaxDynamicSharedMemorySize, SMEM_BYTES);

    mma_qkv_kernel<<<dim3(1152 / 128, NROWS / 128), 256, SMEM_BYTES>>>(hidden, w_qkv, b_qkv);
    attn_kernel<<<NB * NH, 128>>>(mask, table);
    mma_out_kernel<<<dim3(384 / 128, NROWS / 128), 256, SMEM_BYTES>>>(w_out, b_out, out);
}